// round 2
// baseline (speedup 1.0000x reference)
#include <cuda_runtime.h>
#include <cuda_bf16.h>

// Problem constants
#define RANK 4
#define OC   128
#define IC   128
#define KS   3
#define BSZ  32
#define HH   56
#define WW   56
#define HW   (HH*WW)          // 3136
#define ICB  2                // input-channel chunk staged in smem

typedef unsigned long long ull;

// Scratch: combining weights (softmax over rank) and transposed conv weights.
__device__ __align__(16) float g_cw[RANK * HW];                 // [k][y][x]
__device__ __align__(16) float g_wt[IC * KS * KS * OC * RANK];  // [ic][ky][kx][oc][k]

// ---------------- packed f32x2 helpers ----------------
__device__ __forceinline__ ull ffma2(ull a, ull b, ull c) {
    ull d;
    asm("fma.rn.f32x2 %0, %1, %2, %3;" : "=l"(d) : "l"(a), "l"(b), "l"(c));
    return d;
}
__device__ __forceinline__ ull dup2(float v) {
    ull d;
    asm("mov.b64 %0, {%1, %1};" : "=l"(d) : "r"(__float_as_uint(v)));
    return d;
}
__device__ __forceinline__ void unpk(ull a, float& lo, float& hi) {
    unsigned int x, y;
    asm("mov.b64 {%0, %1}, %2;" : "=r"(x), "=r"(y) : "l"(a));
    lo = __uint_as_float(x);
    hi = __uint_as_float(y);
}

// ---------------- prep kernels ----------------
// Softmax over rank of cw_row[k,y] + cw_col[k,x] -> g_cw[k][y*56+x]
__global__ void prep_cw_kernel(const float* __restrict__ cw_row,
                               const float* __restrict__ cw_col) {
    int idx = blockIdx.x * blockDim.x + threadIdx.x;
    if (idx >= HW) return;
    int y = idx / WW, x = idx % WW;
    float v0 = cw_row[0 * HH + y] + cw_col[0 * WW + x];
    float v1 = cw_row[1 * HH + y] + cw_col[1 * WW + x];
    float v2 = cw_row[2 * HH + y] + cw_col[2 * WW + x];
    float v3 = cw_row[3 * HH + y] + cw_col[3 * WW + x];
    float m = fmaxf(fmaxf(v0, v1), fmaxf(v2, v3));
    float e0 = expf(v0 - m), e1 = expf(v1 - m), e2 = expf(v2 - m), e3 = expf(v3 - m);
    float inv = 1.0f / (e0 + e1 + e2 + e3);
    g_cw[0 * HW + idx] = e0 * inv;
    g_cw[1 * HW + idx] = e1 * inv;
    g_cw[2 * HW + idx] = e2 * inv;
    g_cw[3 * HW + idx] = e3 * inv;
}

// Transpose w[k][oc][ic][ky][kx] -> g_wt[ic][ky][kx][oc][k]
__global__ void prep_w_kernel(const float* __restrict__ w) {
    int idx = blockIdx.x * blockDim.x + threadIdx.x;
    if (idx >= IC * KS * KS * OC * RANK) return;
    int k  = idx & 3;
    int t  = idx >> 2;
    int oc = t & 127; t >>= 7;
    int kx = t % 3;   t /= 3;
    int ky = t % 3;   t /= 3;
    int ic = t;
    g_wt[idx] = w[(((size_t)k * OC + oc) * IC + ic) * 9 + ky * 3 + kx];
}

// ---------------- main conv kernel ----------------
// Grid: (7, 14, 32) -> tile 8 cols x 4 rows per block, all 128 oc.
// Block: 256 threads. tid layout:
//   pg  = tid & 7   : r = pg & 3 (row in tile), h = pg >> 2 (col half: 4 cols each)
//   ocg = tid >> 3  : oc0 = ocg*4  (each thread: 4 oc x 4 cols, 4 ranks packed)
__global__ __launch_bounds__(256, 2)
void conv_main_kernel(const float* __restrict__ x,
                      float* __restrict__ out,
                      const float* __restrict__ b_row,
                      const float* __restrict__ b_col,
                      const float* __restrict__ b_ch) {
    __shared__ __align__(16) float s_w[ICB * 9 * OC * RANK];   // 9216 floats = 36 KB
    __shared__ __align__(16) float s_in[ICB][6][12];           // halo 6 rows x 10 cols (pad 12)

    const int tid = threadIdx.x;
    const int r   = tid & 3;
    const int h   = (tid >> 2) & 1;
    const int ocg = tid >> 3;          // 0..31
    const int oc0 = ocg * 4;

    const int bx = blockIdx.x;         // 0..6  (8-col tiles)
    const int by = blockIdx.y;         // 0..13 (4-row tiles)
    const int bb = blockIdx.z;         // batch
    const int xs_blk = bx * 8;         // tile col origin
    const int y0 = by * 4;             // tile row origin
    const int h4 = h * 4;              // this thread's col offset within tile

    ull acc[2][4][4];                  // [rankpair][oc][col]
#pragma unroll
    for (int p = 0; p < 2; p++)
#pragma unroll
        for (int o = 0; o < 4; o++)
#pragma unroll
            for (int c = 0; c < 4; c++) acc[p][o][c] = 0ull;

    const float* xb = x + (size_t)bb * IC * HW;

    for (int ic0 = 0; ic0 < IC; ic0 += ICB) {
        __syncthreads();
        // Stage weights: contiguous 9216 floats from g_wt (coalesced 128-bit copies)
        {
            const float4* src = (const float4*)(g_wt + (size_t)ic0 * (9 * OC * RANK));
            float4* dst = (float4*)s_w;
#pragma unroll
            for (int j = 0; j < 9; j++) dst[tid + j * 256] = src[tid + j * 256];
        }
        // Stage input halo: ICB x 6 x 10 with zero padding at borders
        if (tid < ICB * 60) {
            int ic_l = tid / 60;
            int t    = tid % 60;
            int rr   = t / 10;
            int cc   = t % 10;
            int gy = y0 - 1 + rr;
            int gx = xs_blk - 1 + cc;
            float v = 0.0f;
            if ((unsigned)gy < (unsigned)HH && (unsigned)gx < (unsigned)WW)
                v = xb[(size_t)(ic0 + ic_l) * HW + gy * WW + gx];
            s_in[ic_l][rr][cc] = v;
        }
        __syncthreads();

#pragma unroll
        for (int ic_l = 0; ic_l < ICB; ic_l++) {
#pragma unroll
            for (int ky = 0; ky < 3; ky++) {
                const float4 i03 = *(const float4*)&s_in[ic_l][r + ky][h4];
                const float2 i45 = *(const float2*)&s_in[ic_l][r + ky][h4 + 4];
                ull d[6];
                d[0] = dup2(i03.x); d[1] = dup2(i03.y); d[2] = dup2(i03.z);
                d[3] = dup2(i03.w); d[4] = dup2(i45.x); d[5] = dup2(i45.y);
#pragma unroll
                for (int kx = 0; kx < 3; kx++) {
                    const float* wp = &s_w[(((ic_l * 3 + ky) * 3 + kx) * OC + oc0) * RANK];
                    ulonglong2 w0 = *(const ulonglong2*)(wp + 0);
                    ulonglong2 w1 = *(const ulonglong2*)(wp + 4);
                    ulonglong2 w2 = *(const ulonglong2*)(wp + 8);
                    ulonglong2 w3 = *(const ulonglong2*)(wp + 12);
#pragma unroll
                    for (int c = 0; c < 4; c++) {
                        const ull a = d[c + kx];
                        acc[0][0][c] = ffma2(w0.x, a, acc[0][0][c]);
                        acc[1][0][c] = ffma2(w0.y, a, acc[1][0][c]);
                        acc[0][1][c] = ffma2(w1.x, a, acc[0][1][c]);
                        acc[1][1][c] = ffma2(w1.y, a, acc[1][1][c]);
                        acc[0][2][c] = ffma2(w2.x, a, acc[0][2][c]);
                        acc[1][2][c] = ffma2(w2.y, a, acc[1][2][c]);
                        acc[0][3][c] = ffma2(w3.x, a, acc[0][3][c]);
                        acc[1][3][c] = ffma2(w3.y, a, acc[1][3][c]);
                    }
                }
            }
        }
    }

    // Epilogue: rank-softmax combine + biases, vectorized store.
    const int y  = y0 + r;
    const int xs = xs_blk + h4;
    const float br = b_row[y];

    float cw0[4], cw1[4], cw2[4], cw3[4], bcx[4];
#pragma unroll
    for (int c = 0; c < 4; c++) {
        int idx = y * WW + xs + c;
        cw0[c] = g_cw[0 * HW + idx];
        cw1[c] = g_cw[1 * HW + idx];
        cw2[c] = g_cw[2 * HW + idx];
        cw3[c] = g_cw[3 * HW + idx];
        bcx[c] = b_col[xs + c];
    }
#pragma unroll
    for (int o = 0; o < 4; o++) {
        const float bch = b_ch[oc0 + o];
        float v[4];
#pragma unroll
        for (int c = 0; c < 4; c++) {
            float a0, a1, a2, a3;
            unpk(acc[0][o][c], a0, a1);
            unpk(acc[1][o][c], a2, a3);
            v[c] = cw0[c] * a0 + cw1[c] * a1 + cw2[c] * a2 + cw3[c] * a3
                 + br + bcx[c] + bch;
        }
        float4 st = make_float4(v[0], v[1], v[2], v[3]);
        *(float4*)&out[(((size_t)bb * OC + oc0 + o) * HH + y) * WW + xs] = st;
    }
}

// ---------------- launch ----------------
extern "C" void kernel_launch(void* const* d_in, const int* in_sizes, int n_in,
                              void* d_out, int out_size) {
    const float* x      = (const float*)d_in[0];  // [32,128,56,56]
    const float* w      = (const float*)d_in[1];  // [4,128,128,3,3]
    const float* cw_row = (const float*)d_in[2];  // [4,56,1]
    const float* cw_col = (const float*)d_in[3];  // [4,1,56]
    const float* b_row  = (const float*)d_in[4];  // [1,1,56,1]
    const float* b_col  = (const float*)d_in[5];  // [1,1,1,56]
    const float* b_ch   = (const float*)d_in[6];  // [1,128,1,1]
    float* out = (float*)d_out;

    prep_cw_kernel<<<(HW + 255) / 256, 256>>>(cw_row, cw_col);
    prep_w_kernel<<<(IC * KS * KS * OC * RANK + 255) / 256, 256>>>(w);
    conv_main_kernel<<<dim3(7, 14, 32), 256>>>(x, out, b_row, b_col, b_ch);
}

// round 3
// speedup vs baseline: 1.0013x; 1.0013x over previous
#include <cuda_runtime.h>
#include <cuda_bf16.h>

// Problem constants
#define RANK 4
#define OC   128
#define IC   128
#define KS   3
#define BSZ  32
#define HH   56
#define WW   56
#define HW   (HH*WW)          // 3136
#define ICB  2                // input-channel chunk staged in smem

typedef unsigned long long ull;

// Scratch: combining weights (softmax over rank) and transposed conv weights.
__device__ __align__(16) float g_cw[RANK * HW];                 // [k][y][x]
__device__ __align__(16) float g_wt[IC * KS * KS * OC * RANK];  // [ic][ky][kx][oc][k]

// ---------------- packed f32x2 helpers ----------------
__device__ __forceinline__ ull ffma2(ull a, ull b, ull c) {
    ull d;
    asm("fma.rn.f32x2 %0, %1, %2, %3;" : "=l"(d) : "l"(a), "l"(b), "l"(c));
    return d;
}
__device__ __forceinline__ ull dup2(float v) {
    ull d;
    asm("mov.b64 %0, {%1, %1};" : "=l"(d) : "r"(__float_as_uint(v)));
    return d;
}
__device__ __forceinline__ void unpk(ull a, float& lo, float& hi) {
    unsigned int x, y;
    asm("mov.b64 {%0, %1}, %2;" : "=r"(x), "=r"(y) : "l"(a));
    lo = __uint_as_float(x);
    hi = __uint_as_float(y);
}

// ---------------- prep kernels ----------------
// Softmax over rank of cw_row[k,y] + cw_col[k,x] -> g_cw[k][y*56+x]
__global__ void prep_cw_kernel(const float* __restrict__ cw_row,
                               const float* __restrict__ cw_col) {
    int idx = blockIdx.x * blockDim.x + threadIdx.x;
    if (idx >= HW) return;
    int y = idx / WW, x = idx % WW;
    float v0 = cw_row[0 * HH + y] + cw_col[0 * WW + x];
    float v1 = cw_row[1 * HH + y] + cw_col[1 * WW + x];
    float v2 = cw_row[2 * HH + y] + cw_col[2 * WW + x];
    float v3 = cw_row[3 * HH + y] + cw_col[3 * WW + x];
    float m = fmaxf(fmaxf(v0, v1), fmaxf(v2, v3));
    float e0 = expf(v0 - m), e1 = expf(v1 - m), e2 = expf(v2 - m), e3 = expf(v3 - m);
    float inv = 1.0f / (e0 + e1 + e2 + e3);
    g_cw[0 * HW + idx] = e0 * inv;
    g_cw[1 * HW + idx] = e1 * inv;
    g_cw[2 * HW + idx] = e2 * inv;
    g_cw[3 * HW + idx] = e3 * inv;
}

// Transpose w[k][oc][ic][ky][kx] -> g_wt[ic][ky][kx][oc][k]
__global__ void prep_w_kernel(const float* __restrict__ w) {
    int idx = blockIdx.x * blockDim.x + threadIdx.x;
    if (idx >= IC * KS * KS * OC * RANK) return;
    int k  = idx & 3;
    int t  = idx >> 2;
    int oc = t & 127; t >>= 7;
    int kx = t % 3;   t /= 3;
    int ky = t % 3;   t /= 3;
    int ic = t;
    g_wt[idx] = w[(((size_t)k * OC + oc) * IC + ic) * 9 + ky * 3 + kx];
}

// ---------------- main conv kernel ----------------
// Grid: (7, 14, 32) -> tile 8 cols x 4 rows per block, all 128 oc.
// Block: 256 threads. tid layout:
//   pg  = tid & 7   : r = pg & 3 (row in tile), h = pg >> 2 (col half: 4 cols each)
//   ocg = tid >> 3  : oc0 = ocg*4  (each thread: 4 oc x 4 cols, 4 ranks packed)
__global__ __launch_bounds__(256, 2)
void conv_main_kernel(const float* __restrict__ x,
                      float* __restrict__ out,
                      const float* __restrict__ b_row,
                      const float* __restrict__ b_col,
                      const float* __restrict__ b_ch) {
    __shared__ __align__(16) float s_w[ICB * 9 * OC * RANK];   // 9216 floats = 36 KB
    __shared__ __align__(16) float s_in[ICB][6][12];           // halo 6 rows x 10 cols (pad 12)

    const int tid = threadIdx.x;
    const int r   = tid & 3;
    const int h   = (tid >> 2) & 1;
    const int ocg = tid >> 3;          // 0..31
    const int oc0 = ocg * 4;

    const int bx = blockIdx.x;         // 0..6  (8-col tiles)
    const int by = blockIdx.y;         // 0..13 (4-row tiles)
    const int bb = blockIdx.z;         // batch
    const int xs_blk = bx * 8;         // tile col origin
    const int y0 = by * 4;             // tile row origin
    const int h4 = h * 4;              // this thread's col offset within tile

    ull acc[2][4][4];                  // [rankpair][oc][col]
#pragma unroll
    for (int p = 0; p < 2; p++)
#pragma unroll
        for (int o = 0; o < 4; o++)
#pragma unroll
            for (int c = 0; c < 4; c++) acc[p][o][c] = 0ull;

    const float* xb = x + (size_t)bb * IC * HW;

    for (int ic0 = 0; ic0 < IC; ic0 += ICB) {
        __syncthreads();
        // Stage weights: contiguous 9216 floats from g_wt (coalesced 128-bit copies)
        {
            const float4* src = (const float4*)(g_wt + (size_t)ic0 * (9 * OC * RANK));
            float4* dst = (float4*)s_w;
#pragma unroll
            for (int j = 0; j < 9; j++) dst[tid + j * 256] = src[tid + j * 256];
        }
        // Stage input halo: ICB x 6 x 10 with zero padding at borders
        if (tid < ICB * 60) {
            int ic_l = tid / 60;
            int t    = tid % 60;
            int rr   = t / 10;
            int cc   = t % 10;
            int gy = y0 - 1 + rr;
            int gx = xs_blk - 1 + cc;
            float v = 0.0f;
            if ((unsigned)gy < (unsigned)HH && (unsigned)gx < (unsigned)WW)
                v = xb[(size_t)(ic0 + ic_l) * HW + gy * WW + gx];
            s_in[ic_l][rr][cc] = v;
        }
        __syncthreads();

#pragma unroll
        for (int ic_l = 0; ic_l < ICB; ic_l++) {
#pragma unroll
            for (int ky = 0; ky < 3; ky++) {
                const float4 i03 = *(const float4*)&s_in[ic_l][r + ky][h4];
                const float2 i45 = *(const float2*)&s_in[ic_l][r + ky][h4 + 4];
                ull d[6];
                d[0] = dup2(i03.x); d[1] = dup2(i03.y); d[2] = dup2(i03.z);
                d[3] = dup2(i03.w); d[4] = dup2(i45.x); d[5] = dup2(i45.y);
#pragma unroll
                for (int kx = 0; kx < 3; kx++) {
                    const float* wp = &s_w[(((ic_l * 3 + ky) * 3 + kx) * OC + oc0) * RANK];
                    ulonglong2 w0 = *(const ulonglong2*)(wp + 0);
                    ulonglong2 w1 = *(const ulonglong2*)(wp + 4);
                    ulonglong2 w2 = *(const ulonglong2*)(wp + 8);
                    ulonglong2 w3 = *(const ulonglong2*)(wp + 12);
#pragma unroll
                    for (int c = 0; c < 4; c++) {
                        const ull a = d[c + kx];
                        acc[0][0][c] = ffma2(w0.x, a, acc[0][0][c]);
                        acc[1][0][c] = ffma2(w0.y, a, acc[1][0][c]);
                        acc[0][1][c] = ffma2(w1.x, a, acc[0][1][c]);
                        acc[1][1][c] = ffma2(w1.y, a, acc[1][1][c]);
                        acc[0][2][c] = ffma2(w2.x, a, acc[0][2][c]);
                        acc[1][2][c] = ffma2(w2.y, a, acc[1][2][c]);
                        acc[0][3][c] = ffma2(w3.x, a, acc[0][3][c]);
                        acc[1][3][c] = ffma2(w3.y, a, acc[1][3][c]);
                    }
                }
            }
        }
    }

    // Epilogue: rank-softmax combine + biases, vectorized store.
    const int y  = y0 + r;
    const int xs = xs_blk + h4;
    const float br = b_row[y];

    float cw0[4], cw1[4], cw2[4], cw3[4], bcx[4];
#pragma unroll
    for (int c = 0; c < 4; c++) {
        int idx = y * WW + xs + c;
        cw0[c] = g_cw[0 * HW + idx];
        cw1[c] = g_cw[1 * HW + idx];
        cw2[c] = g_cw[2 * HW + idx];
        cw3[c] = g_cw[3 * HW + idx];
        bcx[c] = b_col[xs + c];
    }
#pragma unroll
    for (int o = 0; o < 4; o++) {
        const float bch = b_ch[oc0 + o];
        float v[4];
#pragma unroll
        for (int c = 0; c < 4; c++) {
            float a0, a1, a2, a3;
            unpk(acc[0][o][c], a0, a1);
            unpk(acc[1][o][c], a2, a3);
            v[c] = cw0[c] * a0 + cw1[c] * a1 + cw2[c] * a2 + cw3[c] * a3
                 + br + bcx[c] + bch;
        }
        float4 st = make_float4(v[0], v[1], v[2], v[3]);
        *(float4*)&out[(((size_t)bb * OC + oc0 + o) * HH + y) * WW + xs] = st;
    }
}

// ---------------- launch ----------------
extern "C" void kernel_launch(void* const* d_in, const int* in_sizes, int n_in,
                              void* d_out, int out_size) {
    const float* x      = (const float*)d_in[0];  // [32,128,56,56]
    const float* w      = (const float*)d_in[1];  // [4,128,128,3,3]
    const float* cw_row = (const float*)d_in[2];  // [4,56,1]
    const float* cw_col = (const float*)d_in[3];  // [4,1,56]
    const float* b_row  = (const float*)d_in[4];  // [1,1,56,1]
    const float* b_col  = (const float*)d_in[5];  // [1,1,1,56]
    const float* b_ch   = (const float*)d_in[6];  // [1,128,1,1]
    float* out = (float*)d_out;

    prep_cw_kernel<<<(HW + 255) / 256, 256>>>(cw_row, cw_col);
    prep_w_kernel<<<(IC * KS * KS * OC * RANK + 255) / 256, 256>>>(w);
    conv_main_kernel<<<dim3(7, 14, 32), 256>>>(x, out, b_row, b_col, b_ch);
}

// round 5
// speedup vs baseline: 2.4762x; 2.4730x over previous
#include <cuda_runtime.h>

typedef unsigned int u32;
typedef unsigned long long u64;

#define RANKS 4
#define OCN   128
#define ICN   128
#define HH    56
#define WW    56
#define HW    3136
#define NST   36
#define KC    32

#define B_STAGE_W (KC*512)            // 16384 words = 65536 B per stage
#define SM_B0 1024
#define SM_B1 (1024 + 65536)
#define SM_A0 (1024 + 131072)         // 132096
#define SM_A1 (SM_A0 + 9216)
#define SM_TOTAL (SM_A1 + 9216)       // 150528

__device__ __align__(16) u32   g_wB[NST * B_STAGE_W];  // tf32, pre-swizzled smem image
__device__ __align__(16) float g_cw[RANKS * HW];       // softmax combine weights

// ---------------- helpers ----------------
__device__ __forceinline__ u32 smem_u32(const void* p) {
    u32 a;
    asm("{ .reg .u64 t; cvta.to.shared.u64 t, %1; cvt.u32.u64 %0, t; }" : "=r"(a) : "l"(p));
    return a;
}
__device__ __forceinline__ u32 cvt_tf32(float v) {
    u32 r;
    asm("cvt.rna.tf32.f32 %0, %1;" : "=r"(r) : "f"(v));
    return r;
}
__device__ __forceinline__ void mbar_init(u32 addr, u32 cnt) {
    asm volatile("mbarrier.init.shared.b64 [%0], %1;" :: "r"(addr), "r"(cnt) : "memory");
}
__device__ __forceinline__ void mbar_expect_tx(u32 addr, u32 bytes) {
    asm volatile("mbarrier.arrive.expect_tx.shared.b64 _, [%0], %1;" :: "r"(addr), "r"(bytes) : "memory");
}
__device__ __forceinline__ void mbar_wait(u32 addr, int phase) {
    asm volatile(
        "{\n\t.reg .pred P;\n"
        "WL_%=:\n\t"
        "mbarrier.try_wait.parity.acquire.cta.shared::cta.b64 P, [%0], %1, 0x989680;\n\t"
        "@P bra.uni WD_%=;\n\t"
        "bra.uni WL_%=;\n\t"
        "WD_%=:\n\t}"
        :: "r"(addr), "r"((u32)phase) : "memory");
}
__device__ __forceinline__ void bulk_copy(u32 dst, const void* src, u32 bytes, u32 mbar) {
    asm volatile(
        "cp.async.bulk.shared::cluster.global.mbarrier::complete_tx::bytes [%0], [%1], %2, [%3];"
        :: "r"(dst), "l"(src), "r"(bytes), "r"(mbar) : "memory");
}
__device__ __forceinline__ void mma_tf32(float& d0, float& d1, float& d2, float& d3,
                                         u32 a0, u32 a1, u32 a2, u32 a3, u32 b0, u32 b1) {
    asm volatile(
        "mma.sync.aligned.m16n8k8.row.col.f32.tf32.tf32.f32 "
        "{%0,%1,%2,%3}, {%4,%5,%6,%7}, {%8,%9}, {%0,%1,%2,%3};"
        : "+f"(d0), "+f"(d1), "+f"(d2), "+f"(d3)
        : "r"(a0), "r"(a1), "r"(a2), "r"(a3), "r"(b0), "r"(b1));
}

// ---------------- prep kernels ----------------
__global__ void prep_cw_kernel(const float* __restrict__ cw_row,
                               const float* __restrict__ cw_col) {
    int idx = blockIdx.x * blockDim.x + threadIdx.x;
    if (idx >= HW) return;
    int y = idx / WW, x = idx % WW;
    float v0 = cw_row[0 * HH + y] + cw_col[0 * WW + x];
    float v1 = cw_row[1 * HH + y] + cw_col[1 * WW + x];
    float v2 = cw_row[2 * HH + y] + cw_col[2 * WW + x];
    float v3 = cw_row[3 * HH + y] + cw_col[3 * WW + x];
    float m = fmaxf(fmaxf(v0, v1), fmaxf(v2, v3));
    float e0 = expf(v0 - m), e1 = expf(v1 - m), e2 = expf(v2 - m), e3 = expf(v3 - m);
    float inv = 1.0f / (e0 + e1 + e2 + e3);
    g_cw[0 * HW + idx] = e0 * inv;
    g_cw[1 * HW + idx] = e1 * inv;
    g_cw[2 * HW + idx] = e2 * inv;
    g_cw[3 * HW + idx] = e3 * inv;
}

// Weights -> tf32 in the exact swizzled smem image.
// Stage s: tap = s>>2 (ky*3+kx), ic = (s&3)*32 + kk.  n = rank*128 + oc.
// smem word (k-row kk, col n): kk*512 + (n ^ ((kk&3)<<3))
__global__ void prep_wB_kernel(const float* __restrict__ w) {
    int idx = blockIdx.x * blockDim.x + threadIdx.x;
    if (idx >= NST * B_STAGE_W) return;
    int n  = idx & 511;
    int kk = (idx >> 9) & 31;
    int s  = idx >> 14;
    int r  = n >> 7, oc = n & 127;
    int tap = s >> 2;
    int ic  = ((s & 3) << 5) + kk;
    float v = w[(((size_t)r * OCN + oc) * ICN + ic) * 9 + tap];
    g_wB[(size_t)s * B_STAGE_W + kk * 512 + (n ^ ((kk & 3) << 3))] = cvt_tf32(v);
}

// ---------------- A im2col staging ----------------
__device__ __forceinline__ void stageA(u32* Ab, const float* __restrict__ xb,
                                       int y, int s, int tid) {
    int tap = s >> 2;
    int dy = tap / 3 - 1, dx = tap % 3 - 1;
    int ic0 = (s & 3) << 5;
    int gy = y + dy;
    bool rowok = (unsigned)gy < 56u;
    const float* src = xb + (size_t)ic0 * HW + gy * WW;
#pragma unroll
    for (int i = 0; i < 4; i++) {
        int idx = i * 512 + tid;
        int px = idx & 63, kk = idx >> 6;
        int gx = px + dx;
        float v = 0.0f;
        if (rowok && (unsigned)gx < 56u) v = src[kk * HW + gx];
        Ab[px * 36 + kk] = cvt_tf32(v);
    }
}

// ---------------- main mma kernel ----------------
// grid (56, 32): output row y, batch. block 512 = 16 warps (4 warp_m x 4 warp_n=rank).
__global__ __launch_bounds__(512, 1)
void conv_mma_kernel(const float* __restrict__ x, float* __restrict__ out,
                     const float* __restrict__ b_row, const float* __restrict__ b_col,
                     const float* __restrict__ b_ch) {
    extern __shared__ char smem[];
    const u32 sbase = smem_u32(smem);
    const int tid = threadIdx.x;
    const int wid = tid >> 5, lane = tid & 31;
    const int warp_m = wid & 3, warp_n = wid >> 2;
    const int g = lane >> 2, t = lane & 3;
    const int y = blockIdx.x;
    const int bb = blockIdx.y;

    if (tid == 0) { mbar_init(sbase + 0, 1); mbar_init(sbase + 8, 1); }
    __syncthreads();

    const float* xb = x + (size_t)bb * ICN * HW;
    float acc[16][4];
#pragma unroll
    for (int i = 0; i < 16; i++)
#pragma unroll
        for (int j = 0; j < 4; j++) acc[i][j] = 0.0f;

    // prologue: stage 0
    if (tid == 0) {
        mbar_expect_tx(sbase + 0, 65536);
        bulk_copy(sbase + SM_B0, g_wB, 65536, sbase + 0);
    }
    stageA((u32*)(smem + SM_A0), xb, y, 0, tid);

    int ph0 = 0, ph1 = 0;
    const int arow0 = (warp_m * 16 + g) * 36;
    const int arow1 = arow0 + 8 * 36;
    const int bcol = warp_n * 128 + g;
    const int txor = t << 3;

    for (int s = 0; s < NST; s++) {
        const int b = s & 1;
        mbar_wait(sbase + b * 8, b ? ph1 : ph0);
        if (b) ph1 ^= 1; else ph0 ^= 1;
        __syncthreads();

        if (s + 1 < NST) {
            if (tid == 0) {
                mbar_expect_tx(sbase + (b ^ 1) * 8, 65536);
                bulk_copy(sbase + (b ? SM_B0 : SM_B1),
                          g_wB + (size_t)(s + 1) * B_STAGE_W, 65536,
                          sbase + (b ^ 1) * 8);
            }
            stageA((u32*)(smem + (b ? SM_A0 : SM_A1)), xb, y, s + 1, tid);
        }

        const u32* Bb = (const u32*)(smem + (b ? SM_B1 : SM_B0));
        const u32* Ab = (const u32*)(smem + (b ? SM_A1 : SM_A0));
#pragma unroll
        for (int ks = 0; ks < 4; ks++) {
            const int ak = ks * 8 + t;
            u32 a0 = Ab[arow0 + ak];
            u32 a1 = Ab[arow1 + ak];
            u32 a2 = Ab[arow0 + ak + 4];
            u32 a3 = Ab[arow1 + ak + 4];
            const u32* b0p = Bb + (ks * 8 + t) * 512 + bcol;
            const u32* b1p = b0p + 4 * 512;
#pragma unroll
            for (int nt = 0; nt < 16; nt++) {
                const int off = (nt << 3) ^ txor;
                mma_tf32(acc[nt][0], acc[nt][1], acc[nt][2], acc[nt][3],
                         a0, a1, a2, a3, b0p[off], b1p[off]);
            }
        }
    }
    __syncthreads();

    // ---- epilogue: rank combine into smem partial [64 px][132] ----
    float* part = (float*)(smem + 1024);
    const int px0 = warp_m * 16 + g, px1 = px0 + 8;
    const float cw0 = g_cw[warp_n * HW + y * WW + px0];                 // px0 <= 55
    const float cw1 = (px1 < 56) ? g_cw[warp_n * HW + y * WW + px1] : 0.0f;

#pragma unroll
    for (int pass = 0; pass < 4; pass++) {
        if (warp_n == pass) {
#pragma unroll
            for (int nt = 0; nt < 16; nt++) {
                const int oc = nt * 8 + 2 * t;
                float* p0 = &part[px0 * 132 + oc];
                float* p1 = &part[px1 * 132 + oc];
                if (pass == 0) {
                    p0[0] = cw0 * acc[nt][0]; p0[1] = cw0 * acc[nt][1];
                    p1[0] = cw1 * acc[nt][2]; p1[1] = cw1 * acc[nt][3];
                } else {
                    p0[0] += cw0 * acc[nt][0]; p0[1] += cw0 * acc[nt][1];
                    p1[0] += cw1 * acc[nt][2]; p1[1] += cw1 * acc[nt][3];
                }
            }
        }
        __syncthreads();
    }

    // ---- biases + store ----
    const float br = b_row[y];
    for (int idx = tid; idx < OCN * 56; idx += 512) {
        const int oc = idx / 56, xx = idx - oc * 56;
        out[((size_t)(bb * OCN + oc) * HH + y) * WW + xx] =
            part[xx * 132 + oc] + br + b_col[xx] + b_ch[oc];
    }
}

// ---------------- launch ----------------
extern "C" void kernel_launch(void* const* d_in, const int* in_sizes, int n_in,
                              void* d_out, int out_size) {
    const float* x      = (const float*)d_in[0];  // [32,128,56,56]
    const float* w      = (const float*)d_in[1];  // [4,128,128,3,3]
    const float* cw_row = (const float*)d_in[2];  // [4,56,1]
    const float* cw_col = (const float*)d_in[3];  // [4,1,56]
    const float* b_row  = (const float*)d_in[4];  // [1,1,56,1]
    const float* b_col  = (const float*)d_in[5];  // [1,1,1,56]
    const float* b_ch   = (const float*)d_in[6];  // [1,128,1,1]
    float* out = (float*)d_out;

    cudaFuncSetAttribute(conv_mma_kernel,
                         cudaFuncAttributeMaxDynamicSharedMemorySize, SM_TOTAL);

    prep_cw_kernel<<<(HW + 255) / 256, 256>>>(cw_row, cw_col);
    prep_wB_kernel<<<(NST * B_STAGE_W + 255) / 256, 256>>>(w);
    conv_mma_kernel<<<dim3(56, 32), 512, SM_TOTAL>>>(x, out, b_row, b_col, b_ch);
}